// round 7
// baseline (speedup 1.0000x reference)
#include <cuda_runtime.h>
#include <cuda_bf16.h>
#include <cstdint>

// B=256, NU=NL=QU=QL=64. One CTA = ONE batch row. 256 CTAs x 256 threads,
// ~106 KB smem each -> 2 CTAs co-resident per SM (independent barrier domains).
#define THREADS 256

// ---------------- smem byte offsets (all tiles SW128-swizzled) --------------
#define SM_P    0u          // [64 rows k][64 bf16]          8 KB
#define SM_U    8192u       // [256 rows (l*4+n)][64 bf16]  32 KB
#define SM_C1   40960u      // [64 rows l][64 bf16 (k)]      8 KB each
#define SM_C2   49152u
#define SM_C3   57344u
#define SM_C4   65536u
#define SM_TH   73728u      // [64 j][64 bf16] 8 KB each
#define SM_T2   81920u
#define SM_T3   90112u
#define SM_T4   98304u
#define SM_LS   SM_U        // overlay: [64 l][65 f32] = 16640 B (U dead)
#define SM_MISC 106496u
#define SMEM_TOTAL (SM_MISC + 1536u)   // 108032 B -> 2 CTAs/SM

__device__ __forceinline__ uint32_t sw128(uint32_t o) { return o ^ ((o >> 3) & 0x70u); }

__device__ __forceinline__ uint32_t smem_u32(const void* p) {
    uint32_t a;
    asm("{ .reg .u64 t; cvta.to.shared.u64 t, %1; cvt.u32.u64 %0, t; }" : "=r"(a) : "l"(p));
    return a;
}

// m16n8k16 row.col bf16 -> f32 (sm_80-baseline PTX; HMMA on Blackwell)
__device__ __forceinline__ void mma16816(float acc[4], const uint32_t a[4],
                                         uint32_t b0, uint32_t b1) {
    asm volatile(
        "mma.sync.aligned.m16n8k16.row.col.f32.bf16.bf16.f32 "
        "{%0,%1,%2,%3}, {%4,%5,%6,%7}, {%8,%9}, {%0,%1,%2,%3};"
        : "+f"(acc[0]), "+f"(acc[1]), "+f"(acc[2]), "+f"(acc[3])
        : "r"(a[0]), "r"(a[1]), "r"(a[2]), "r"(a[3]), "r"(b0), "r"(b1));
}

__device__ __forceinline__ void ldmx4(uint32_t r[4], uint32_t addr) {
    asm volatile("ldmatrix.sync.aligned.m8n8.x4.shared.b16 {%0,%1,%2,%3}, [%4];"
                 : "=r"(r[0]), "=r"(r[1]), "=r"(r[2]), "=r"(r[3]) : "r"(addr));
}

__global__ void __launch_bounds__(THREADS, 2)
drn_fused(const float* __restrict__ P, const float* __restrict__ weight,
          const float* __restrict__ bias_abs, const float* __restrict__ bias_q,
          const float* __restrict__ lam_abs, const float* __restrict__ lam_q,
          float* __restrict__ out)
{
    extern __shared__ __align__(16) char sm[];
    const uint32_t smb = smem_u32(sm);
    float* a0inv = (float*)(sm + SM_MISC);          // 64 floats
    float* sBa   = (float*)(sm + SM_MISC + 256);
    float* sBq   = (float*)(sm + SM_MISC + 512);
    float* sLa   = (float*)(sm + SM_MISC + 768);
    float* sLq   = (float*)(sm + SM_MISC + 1024);

    const int tid = threadIdx.x;
    const int i   = blockIdx.x;

    // ---- fill P tile (bf16) + row sums (4 threads per row) -----------------
    {
        const int r = tid >> 2, qh = tid & 3;
        const float* src = P + ((size_t)i * 64 + r) * 64 + qh * 16;
        float s = 0.f;
        #pragma unroll
        for (int q = 0; q < 4; ++q) {
            const float4 f = ((const float4*)src)[q];
            s += f.x + f.y + f.z + f.w;
            const uint32_t off = (uint32_t)r * 128 + (qh * 16 + q * 4) * 2;
            *(__nv_bfloat162*)(sm + SM_P + sw128(off))     = __floats2bfloat162_rn(f.x, f.y);
            *(__nv_bfloat162*)(sm + SM_P + sw128(off + 4)) = __floats2bfloat162_rn(f.z, f.w);
        }
        s += __shfl_xor_sync(0xffffffffu, s, 1);
        s += __shfl_xor_sync(0xffffffffu, s, 2);
        if (qh == 0) a0inv[r] = 1.0f / s;
    }

    // ---- fill U table: row r = l*4+n holds u^(n+1), u=((l-m)/64)^2 ---------
    {
        const int r = tid, l = r >> 2, n = r & 3;
        #pragma unroll 4
        for (int m2 = 0; m2 < 32; ++m2) {
            const int m = m2 * 2;
            float d0 = (float)(l - m) * (1.f / 64.f);
            float d1 = (float)(l - m - 1) * (1.f / 64.f);
            float u0 = d0 * d0, u1 = d1 * d1;
            float w0 = u0 * u0, w1 = u1 * u1;
            float v0 = (n == 0) ? u0 : (n == 1) ? w0 : (n == 2) ? w0 * u0 : w0 * w0;
            float v1 = (n == 0) ? u1 : (n == 1) ? w1 : (n == 2) ? w1 * u1 : w1 * w1;
            const uint32_t off = (uint32_t)r * 128 + m * 2;
            *(__nv_bfloat162*)(sm + SM_U + sw128(off)) = __floats2bfloat162_rn(v0, v1);
        }
    }

    // ---- fill T power tiles: row j holds t^n[j,k], t = -w ------------------
    {
        const int j = tid >> 2, kq = (tid & 3) * 16;
        const float* wr = weight + j * 64 + kq;
        #pragma unroll
        for (int q = 0; q < 8; ++q) {
            const float t0 = -wr[q * 2], t1 = -wr[q * 2 + 1];
            const float s0 = t0 * t0,   s1 = t1 * t1;
            const uint32_t off = (uint32_t)j * 128 + (kq + q * 2) * 2;
            *(__nv_bfloat162*)(sm + SM_TH + sw128(off)) = __floats2bfloat162_rn(t0, t1);
            *(__nv_bfloat162*)(sm + SM_T2 + sw128(off)) = __floats2bfloat162_rn(s0, s1);
            *(__nv_bfloat162*)(sm + SM_T3 + sw128(off)) = __floats2bfloat162_rn(s0 * t0, s1 * t1);
            *(__nv_bfloat162*)(sm + SM_T4 + sw128(off)) = __floats2bfloat162_rn(s0 * s0, s1 * s1);
        }
    }
    if (tid < 64) {
        sBa[tid] = bias_abs[tid]; sBq[tid] = bias_q[tid];
        sLa[tid] = lam_abs[tid];  sLq[tid] = lam_q[tid];
    }
    __syncthreads();

    const int lane = tid & 31, wid = tid >> 5;
    const int g = lane >> 2, c = lane & 3;
    const int mw = wid & 1, nq = wid >> 1;   // M-half (32 rows), N-quarter
    const int mr = mw * 32;

    // ldmatrix lane->address maps (relative byte offsets, pre-swizzle)
    const uint32_t aRow = (uint32_t)((lane & 7) + ((lane >> 3) & 1) * 8) * 128
                          + (uint32_t)(lane >> 4) * 16;
    const uint32_t bRow = (uint32_t)((lane & 7) + (lane >> 4) * 8) * 128
                          + (uint32_t)((lane >> 3) & 1) * 16;

    // Hoisted A fragments (P tile rows mr..mr+32), invariant over GEMM1
    uint32_t afr[2][4][4];
    #pragma unroll
    for (int mt = 0; mt < 2; ++mt)
        #pragma unroll
        for (int ks = 0; ks < 4; ++ks)
            ldmx4(afr[mt][ks],
                  smb + SM_P + sw128((uint32_t)(mr + mt * 16) * 128 + aRow + ks * 32));

    // ================= GEMM1: moments -> cumulants -> C tiles ===============
    #pragma unroll 1
    for (int nbp = 0; nbp < 4; ++nbp) {
        float acc[2][2][4];
        #pragma unroll
        for (int mt = 0; mt < 2; ++mt)
            #pragma unroll
            for (int bk = 0; bk < 2; ++bk)
                acc[mt][bk][0] = acc[mt][bk][1] = acc[mt][bk][2] = acc[mt][bk][3] = 0.f;

        #pragma unroll
        for (int ks = 0; ks < 4; ++ks) {
            uint32_t b[4];
            ldmx4(b, smb + SM_U + sw128((uint32_t)(nq * 64 + nbp * 16) * 128
                                        + bRow + ks * 32));
            #pragma unroll
            for (int mt = 0; mt < 2; ++mt) {
                mma16816(acc[mt][0], afr[mt][ks], b[0], b[1]);
                mma16816(acc[mt][1], afr[mt][ks], b[2], b[3]);
            }
        }
        // epilogue: lane-pair exchange, fp32 cumulants, bf16 C stores
        #pragma unroll
        for (int mt = 0; mt < 2; ++mt) {
            #pragma unroll
            for (int bk = 0; bk < 2; ++bk) {
                float* a = acc[mt][bk];
                const float r0 = __shfl_xor_sync(0xffffffffu, a[0], 1);
                const float r1 = __shfl_xor_sync(0xffffffffu, a[1], 1);
                const float r2 = __shfl_xor_sync(0xffffffffu, a[2], 1);
                const float r3 = __shfl_xor_sync(0xffffffffu, a[3], 1);
                int row; float M1, M2, M3, M4;
                if ((c & 1) == 0) { row = mr + mt * 16 + g;     M1 = a[0]; M2 = a[1]; M3 = r0; M4 = r1; }
                else              { row = mr + mt * 16 + g + 8; M1 = r2; M2 = r3; M3 = a[2]; M4 = a[3]; }
                const int l = nq * 16 + nbp * 4 + bk * 2 + (c >> 1);
                const float ai = a0inv[row];
                const float m1 = M1 * ai, m2 = M2 * ai, m3 = M3 * ai, m4 = M4 * ai;
                const float m1s = m1 * m1;
                const float c2 = 0.5f * (m2 - m1s);
                const float c3 = (1.f / 6.f) * (m3 - 3.f * m1 * m2 + 2.f * m1s * m1);
                const float c4 = (1.f / 24.f) * (m4 - 4.f * m1 * m3 - 3.f * m2 * m2
                                                 + 12.f * m1s * m2 - 6.f * m1s * m1s);
                const uint32_t off = (uint32_t)(l * 128 + row * 2);
                *(__nv_bfloat16*)(sm + SM_C1 + sw128(off)) = __float2bfloat16_rn(m1);
                *(__nv_bfloat16*)(sm + SM_C2 + sw128(off)) = __float2bfloat16_rn(c2);
                *(__nv_bfloat16*)(sm + SM_C3 + sw128(off)) = __float2bfloat16_rn(c3);
                *(__nv_bfloat16*)(sm + SM_C4 + sw128(off)) = __float2bfloat16_rn(c4);
            }
        }
    }
    __syncthreads();

    // ================= GEMM2: logsum^T[l, j] =================================
    {
        float acc[2][2][4];
        #pragma unroll
        for (int mt = 0; mt < 2; ++mt)
            #pragma unroll
            for (int bk = 0; bk < 2; ++bk)
                acc[mt][bk][0] = acc[mt][bk][1] = acc[mt][bk][2] = acc[mt][bk][3] = 0.f;

        const uint32_t pA[4] = {SM_C1, SM_C2, SM_C3, SM_C4};
        const uint32_t pB[4] = {SM_TH, SM_T2, SM_T3, SM_T4};
        #pragma unroll 1
        for (int p = 0; p < 4; ++p) {
            #pragma unroll
            for (int ks = 0; ks < 4; ++ks) {
                uint32_t b[4];
                ldmx4(b, smb + pB[p] + sw128((uint32_t)(nq * 16) * 128 + bRow + ks * 32));
                #pragma unroll
                for (int mt = 0; mt < 2; ++mt) {
                    uint32_t a[4];
                    ldmx4(a, smb + pA[p] + sw128((uint32_t)(mr + mt * 16) * 128
                                                 + aRow + ks * 32));
                    mma16816(acc[mt][0], a, b[0], b[1]);
                    mma16816(acc[mt][1], a, b[2], b[3]);
                }
            }
        }

        // epilogue: + exponent_B, stage to sLs (overlaid on U)
        float* ls = (float*)(sm + SM_LS);
        #pragma unroll
        for (int mt = 0; mt < 2; ++mt) {
            const int rowA = mr + mt * 16 + g, rowB = rowA + 8;
            const float slA = (float)rowA * (1.f / 64.f);
            const float slB = (float)rowB * (1.f / 64.f);
            #pragma unroll
            for (int bk = 0; bk < 2; ++bk) {
                const float* a = acc[mt][bk];
                const int j0 = nq * 16 + bk * 8 + c * 2, j1 = j0 + 1;
                const float bq0 = sBq[j0], lq0 = sLq[j0], ba0 = sBa[j0], la0 = sLa[j0];
                const float bq1 = sBq[j1], lq1 = sLq[j1], ba1 = sBa[j1], la1 = sLa[j1];
                float d;
                d = slA - lq0; ls[rowA * 65 + j0] = a[0] - bq0 * d * d - ba0 * fabsf(slA - la0);
                d = slA - lq1; ls[rowA * 65 + j1] = a[1] - bq1 * d * d - ba1 * fabsf(slA - la1);
                d = slB - lq0; ls[rowB * 65 + j0] = a[2] - bq0 * d * d - ba0 * fabsf(slB - la0);
                d = slB - lq1; ls[rowB * 65 + j1] = a[3] - bq1 * d * d - ba1 * fabsf(slB - la1);
            }
        }
    }
    __syncthreads();

    // ================= softmax over l, write out (4 threads per row j) ======
    {
        const float* ls = (const float*)(sm + SM_LS);
        const int j = tid >> 2, h = tid & 3;
        float v[16], mx = -1e30f;
        #pragma unroll
        for (int q = 0; q < 16; ++q) {
            v[q] = ls[(h * 16 + q) * 65 + j];
            mx = fmaxf(mx, v[q]);
        }
        mx = fmaxf(mx, __shfl_xor_sync(0xffffffffu, mx, 1));
        mx = fmaxf(mx, __shfl_xor_sync(0xffffffffu, mx, 2));
        float s = 0.f;
        #pragma unroll
        for (int q = 0; q < 16; ++q) { v[q] = __expf(v[q] - mx); s += v[q]; }
        s += __shfl_xor_sync(0xffffffffu, s, 1);
        s += __shfl_xor_sync(0xffffffffu, s, 2);
        const float inv = 1.0f / s;
        float4* ob = (float4*)(out + ((size_t)i * 64 + j) * 64 + h * 16);
        #pragma unroll
        for (int q = 0; q < 4; ++q)
            ob[q] = make_float4(v[4 * q] * inv, v[4 * q + 1] * inv,
                                v[4 * q + 2] * inv, v[4 * q + 3] * inv);
    }
}

// ---------------------------------------------------------------------------
extern "C" void kernel_launch(void* const* d_in, const int* in_sizes, int n_in,
                              void* d_out, int out_size)
{
    const float* P        = (const float*)d_in[0];
    const float* weight   = (const float*)d_in[1];
    const float* bias_abs = (const float*)d_in[2];
    const float* bias_q   = (const float*)d_in[3];
    const float* lam_abs  = (const float*)d_in[4];
    const float* lam_q    = (const float*)d_in[5];
    float* out = (float*)d_out;

    cudaFuncSetAttribute(drn_fused, cudaFuncAttributeMaxDynamicSharedMemorySize,
                         SMEM_TOTAL);
    drn_fused<<<256, THREADS, SMEM_TOTAL>>>(P, weight, bias_abs, bias_q,
                                            lam_abs, lam_q, out);
}

// round 9
// speedup vs baseline: 1.4298x; 1.4298x over previous
#include <cuda_runtime.h>
#include <cuda_bf16.h>
#include <cstdint>

// B=256, NU=NL=QU=QL=64. One CTA = 2 batch rows. 128 CTAs x 512 threads.
#define THREADS 512

// ---------------- CTA-invariant tables, built once by drn_prep --------------
// layout: U (32768 B, swizzled bf16) | T1,T2,T3,T4 (4 x 8192 B, swizzled bf16)
//         | EB (64 x 66 f32 = 16896 B)
#define GP_U   0u
#define GP_T   32768u
#define GP_EB  65536u
#define GP_SIZE 82432u
__device__ __align__(16) unsigned char g_prep[GP_SIZE];

// ---------------- smem byte offsets -----------------------------------------
#define SM_P    0u          // [128 rows (ii,k)][64 bf16]   16 KB
#define SM_U    16384u      // copy of GP block (U,T,EB contiguous)
#define SM_TH   49152u
#define SM_T2   57344u
#define SM_T3   65536u
#define SM_T4   73728u
#define SM_EB   81920u      // [64 l][66 f32]
#define SM_C1   99328u      // [128 rows (ii*64+l)][64 bf16] 16 KB each
#define SM_C2   115712u
#define SM_C3   132096u
#define SM_C4   148480u
#define SM_LS   0u          // overlay [128][65] f32 = 33280 B (P,U dead)
#define SM_MISC 164864u     // a0inv: 128 f32
#define SMEM_TOTAL 165376u

__device__ __forceinline__ uint32_t sw128(uint32_t o) { return o ^ ((o >> 3) & 0x70u); }

__device__ __forceinline__ uint32_t smem_u32(const void* p) {
    uint32_t a;
    asm("{ .reg .u64 t; cvta.to.shared.u64 t, %1; cvt.u32.u64 %0, t; }" : "=r"(a) : "l"(p));
    return a;
}

// m16n8k16 row.col bf16 -> f32 (sm_80-baseline PTX; HMMA on Blackwell)
__device__ __forceinline__ void mma16816(float acc[4], const uint32_t a[4],
                                         uint32_t b0, uint32_t b1) {
    asm volatile(
        "mma.sync.aligned.m16n8k16.row.col.f32.bf16.bf16.f32 "
        "{%0,%1,%2,%3}, {%4,%5,%6,%7}, {%8,%9}, {%0,%1,%2,%3};"
        : "+f"(acc[0]), "+f"(acc[1]), "+f"(acc[2]), "+f"(acc[3])
        : "r"(a[0]), "r"(a[1]), "r"(a[2]), "r"(a[3]), "r"(b0), "r"(b1));
}

__device__ __forceinline__ void ldmx4(uint32_t r[4], uint32_t addr) {
    asm volatile("ldmatrix.sync.aligned.m8n8.x4.shared.b16 {%0,%1,%2,%3}, [%4];"
                 : "=r"(r[0]), "=r"(r[1]), "=r"(r[2]), "=r"(r[3]) : "r"(addr));
}

#define CP_ASYNC16(dst, src) \
    asm volatile("cp.async.cg.shared.global [%0], [%1], 16;" :: "r"(dst), "l"(src))
#define CP_COMMIT() asm volatile("cp.async.commit_group;")
#define CP_WAIT0()  asm volatile("cp.async.wait_group 0;")

// ============================================================================
// Prep kernel: build U powers, T weight-powers, exponent_B once.
// ============================================================================
__global__ void __launch_bounds__(256)
drn_prep(const float* __restrict__ weight, const float* __restrict__ bias_abs,
         const float* __restrict__ bias_q, const float* __restrict__ lam_abs,
         const float* __restrict__ lam_q)
{
    const int idx = blockIdx.x * 256 + threadIdx.x;
    if (idx < 16384) {
        // U: row r = l*4+n holds u^(n+1), u = ((l-m)/64)^2
        const int r = idx >> 6, m = idx & 63, l = r >> 2, n = r & 3;
        const float d = (float)(l - m) * (1.f / 64.f);
        const float u = d * d, w = u * u;
        const float v = (n == 0) ? u : (n == 1) ? w : (n == 2) ? w * u : w * w;
        *(__nv_bfloat16*)(g_prep + GP_U + sw128((uint32_t)(r * 128 + m * 2))) =
            __float2bfloat16_rn(v);
    } else if (idx < 20480) {
        // T: row j holds t^n[j,k], t = -w
        const int e = idx - 16384, j = e >> 6, k = e & 63;
        const float t = -weight[j * 64 + k];
        const float s = t * t;
        const uint32_t off = sw128((uint32_t)(j * 128 + k * 2));
        *(__nv_bfloat16*)(g_prep + GP_T + off)         = __float2bfloat16_rn(t);
        *(__nv_bfloat16*)(g_prep + GP_T + 8192 + off)  = __float2bfloat16_rn(s);
        *(__nv_bfloat16*)(g_prep + GP_T + 16384 + off) = __float2bfloat16_rn(s * t);
        *(__nv_bfloat16*)(g_prep + GP_T + 24576 + off) = __float2bfloat16_rn(s * s);
    } else if (idx < 24576) {
        // EB[l][j] = -bq[j]*(sl-lq[j])^2 - ba[j]*|sl-la[j]|  (stride 66)
        const int e = idx - 20480, l = e >> 6, j = e & 63;
        const float sl = (float)l * (1.f / 64.f);
        const float dq = sl - lam_q[j], da = sl - lam_abs[j];
        ((float*)(g_prep + GP_EB))[l * 66 + j] =
            -bias_q[j] * dq * dq - bias_abs[j] * fabsf(da);
    }
}

// ============================================================================
// Main fused kernel.
// ============================================================================
__global__ void __launch_bounds__(THREADS, 1)
drn_fused(const float* __restrict__ P, float* __restrict__ out)
{
    extern __shared__ __align__(16) char sm[];
    const uint32_t smb = smem_u32(sm);
    float* a0inv = (float*)(sm + SM_MISC);          // 128 floats

    const int tid = threadIdx.x;
    const int i0  = blockIdx.x * 2;

    // ---- kick off bulk copy of invariant tables (overlaps P fill) ----------
    {
        const unsigned char* gp = g_prep;
        for (uint32_t off = (uint32_t)tid * 16; off < GP_SIZE; off += THREADS * 16)
            CP_ASYNC16(smb + SM_U + off, gp + off);
        CP_COMMIT();
    }

    // ---- fill P tile (bf16) + row sums (4 threads per row) -----------------
    {
        const int r = tid >> 2, qh = tid & 3;
        const float* src = P + ((size_t)(i0 + (r >> 6)) * 64 + (r & 63)) * 64 + qh * 16;
        float s = 0.f;
        #pragma unroll
        for (int q = 0; q < 4; ++q) {
            const float4 f = ((const float4*)src)[q];
            s += f.x + f.y + f.z + f.w;
            const uint32_t off = (uint32_t)r * 128 + (qh * 16 + q * 4) * 2;
            *(__nv_bfloat162*)(sm + SM_P + sw128(off))     = __floats2bfloat162_rn(f.x, f.y);
            *(__nv_bfloat162*)(sm + SM_P + sw128(off + 4)) = __floats2bfloat162_rn(f.z, f.w);
        }
        s += __shfl_xor_sync(0xffffffffu, s, 1);
        s += __shfl_xor_sync(0xffffffffu, s, 2);
        if (qh == 0) a0inv[r] = 1.0f / s;
    }
    CP_WAIT0();
    __syncthreads();

    const int lane = tid & 31, wid = tid >> 5;
    const int g = lane >> 2, c = lane & 3;
    const int mw = wid & 3, nq = wid >> 2;   // M-tile group (M=32), N-quarter
    const int mr = mw * 32;

    // ldmatrix lane->address maps (relative byte offsets, pre-swizzle)
    const uint32_t aRow = (uint32_t)((lane & 7) + ((lane >> 3) & 1) * 8) * 128
                          + (uint32_t)(lane >> 4) * 16;
    const uint32_t bRow = (uint32_t)((lane & 7) + (lane >> 4) * 8) * 128
                          + (uint32_t)((lane >> 3) & 1) * 16;

    // Hoisted A fragments (P tile rows mr..mr+32), invariant over GEMM1
    uint32_t afr[2][4][4];
    #pragma unroll
    for (int mt = 0; mt < 2; ++mt)
        #pragma unroll
        for (int ks = 0; ks < 4; ++ks)
            ldmx4(afr[mt][ks],
                  smb + SM_P + sw128((uint32_t)(mr + mt * 16) * 128 + aRow + ks * 32));

    // ================= GEMM1: moments -> cumulants -> C tiles ===============
    #pragma unroll 1
    for (int nbp = 0; nbp < 4; ++nbp) {
        float acc[2][2][4];
        #pragma unroll
        for (int mt = 0; mt < 2; ++mt)
            #pragma unroll
            for (int bk = 0; bk < 2; ++bk)
                acc[mt][bk][0] = acc[mt][bk][1] = acc[mt][bk][2] = acc[mt][bk][3] = 0.f;

        #pragma unroll
        for (int ks = 0; ks < 4; ++ks) {
            uint32_t b[4];
            ldmx4(b, smb + SM_U + sw128((uint32_t)(nq * 64 + nbp * 16) * 128
                                        + bRow + ks * 32));
            #pragma unroll
            for (int mt = 0; mt < 2; ++mt) {
                mma16816(acc[mt][0], afr[mt][ks], b[0], b[1]);
                mma16816(acc[mt][1], afr[mt][ks], b[2], b[3]);
            }
        }
        // epilogue: 2-shfl lane-pair exchange, fp32 cumulants, bf16 C stores
        // even lane owns M1,M2 (rows g, g+8); odd lane owns M3,M4.
        // even sends a[2],a[3] (M1,M2 of g+8); odd sends a[0],a[1] (M3,M4 of g).
        #pragma unroll
        for (int mt = 0; mt < 2; ++mt) {
            #pragma unroll
            for (int bk = 0; bk < 2; ++bk) {
                float* a = acc[mt][bk];
                const bool odd = (c & 1);
                const float v1 = odd ? a[0] : a[2];
                const float v2 = odd ? a[1] : a[3];
                const float w1 = __shfl_xor_sync(0xffffffffu, v1, 1);
                const float w2 = __shfl_xor_sync(0xffffffffu, v2, 1);
                const int row = mr + mt * 16 + g + (odd ? 8 : 0);
                const float M1 = odd ? w1 : a[0];
                const float M2 = odd ? w2 : a[1];
                const float M3 = odd ? a[2] : w1;
                const float M4 = odd ? a[3] : w2;
                const int l = nq * 16 + nbp * 4 + bk * 2 + (c >> 1);
                const float ai = a0inv[row];
                const float m1 = M1 * ai, m2 = M2 * ai, m3 = M3 * ai, m4 = M4 * ai;
                const float m1s = m1 * m1;
                const float c2 = 0.5f * (m2 - m1s);
                const float c3 = (1.f / 6.f) * (m3 - 3.f * m1 * m2 + 2.f * m1s * m1);
                const float c4 = (1.f / 24.f) * (m4 - 4.f * m1 * m3 - 3.f * m2 * m2
                                                 + 12.f * m1s * m2 - 6.f * m1s * m1s);
                const uint32_t off =
                    (uint32_t)(((row >> 6) * 64 + l) * 128 + (row & 63) * 2);
                *(__nv_bfloat16*)(sm + SM_C1 + sw128(off)) = __float2bfloat16_rn(m1);
                *(__nv_bfloat16*)(sm + SM_C2 + sw128(off)) = __float2bfloat16_rn(c2);
                *(__nv_bfloat16*)(sm + SM_C3 + sw128(off)) = __float2bfloat16_rn(c3);
                *(__nv_bfloat16*)(sm + SM_C4 + sw128(off)) = __float2bfloat16_rn(c4);
            }
        }
    }
    __syncthreads();

    // ================= GEMM2: logsum^T[(ii,l), j] ============================
    {
        float acc[2][2][4];
        #pragma unroll
        for (int mt = 0; mt < 2; ++mt)
            #pragma unroll
            for (int bk = 0; bk < 2; ++bk)
                acc[mt][bk][0] = acc[mt][bk][1] = acc[mt][bk][2] = acc[mt][bk][3] = 0.f;

        const uint32_t pA[4] = {SM_C1, SM_C2, SM_C3, SM_C4};
        const uint32_t pB[4] = {SM_TH, SM_T2, SM_T3, SM_T4};
        #pragma unroll 1
        for (int p = 0; p < 4; ++p) {
            #pragma unroll
            for (int ks = 0; ks < 4; ++ks) {
                uint32_t b[4];
                ldmx4(b, smb + pB[p] + sw128((uint32_t)(nq * 16) * 128 + bRow + ks * 32));
                #pragma unroll
                for (int mt = 0; mt < 2; ++mt) {
                    uint32_t a[4];
                    ldmx4(a, smb + pA[p] + sw128((uint32_t)(mr + mt * 16) * 128
                                                 + aRow + ks * 32));
                    mma16816(acc[mt][0], a, b[0], b[1]);
                    mma16816(acc[mt][1], a, b[2], b[3]);
                }
            }
        }

        // epilogue: + EB table, stage to LS (overlays dead P/U regions)
        float* ls = (float*)(sm + SM_LS);
        const float* eb = (const float*)(sm + SM_EB);
        #pragma unroll
        for (int mt = 0; mt < 2; ++mt) {
            const int rowA = mr + mt * 16 + g, rowB = rowA + 8;
            const int lA = rowA & 63, lB = rowB & 63;
            #pragma unroll
            for (int bk = 0; bk < 2; ++bk) {
                const float* a = acc[mt][bk];
                const int j0 = nq * 16 + bk * 8 + c * 2;
                const float2 eA = *(const float2*)&eb[lA * 66 + j0];
                const float2 eB = *(const float2*)&eb[lB * 66 + j0];
                ls[rowA * 65 + j0]     = a[0] + eA.x;
                ls[rowA * 65 + j0 + 1] = a[1] + eA.y;
                ls[rowB * 65 + j0]     = a[2] + eB.x;
                ls[rowB * 65 + j0 + 1] = a[3] + eB.y;
            }
        }
    }
    __syncthreads();

    // ====== softmax over l (no max pass: |logits| <= ~4, fp32-safe) =========
    {
        const float* ls = (const float*)(sm + SM_LS);
        const int rid = tid >> 2, h = tid & 3;
        const int ii = rid >> 6, j = rid & 63;
        const int base = ii * 64 + h * 16;
        float v[16], s = 0.f;
        #pragma unroll
        for (int q = 0; q < 16; ++q) {
            v[q] = __expf(ls[(base + q) * 65 + j]);
            s += v[q];
        }
        s += __shfl_xor_sync(0xffffffffu, s, 1);
        s += __shfl_xor_sync(0xffffffffu, s, 2);
        const float inv = 1.0f / s;
        float4* ob = (float4*)(out + ((size_t)(i0 + ii) * 64 + j) * 64 + h * 16);
        #pragma unroll
        for (int q = 0; q < 4; ++q)
            ob[q] = make_float4(v[4 * q] * inv, v[4 * q + 1] * inv,
                                v[4 * q + 2] * inv, v[4 * q + 3] * inv);
    }
}

// ---------------------------------------------------------------------------
extern "C" void kernel_launch(void* const* d_in, const int* in_sizes, int n_in,
                              void* d_out, int out_size)
{
    const float* P        = (const float*)d_in[0];
    const float* weight   = (const float*)d_in[1];
    const float* bias_abs = (const float*)d_in[2];
    const float* bias_q   = (const float*)d_in[3];
    const float* lam_abs  = (const float*)d_in[4];
    const float* lam_q    = (const float*)d_in[5];
    float* out = (float*)d_out;

    cudaFuncSetAttribute(drn_fused, cudaFuncAttributeMaxDynamicSharedMemorySize,
                         SMEM_TOTAL);
    drn_prep<<<96, 256>>>(weight, bias_abs, bias_q, lam_abs, lam_q);
    drn_fused<<<128, THREADS, SMEM_TOTAL>>>(P, out);
}